// round 3
// baseline (speedup 1.0000x reference)
#include <cuda_runtime.h>

#define N_POSN 8192
#define NB     4
#define NG     512
#define NJ     2048   /* NB*NG */
#define EPSF   1e-6f

// ---------------- device scratch (allocation-free) ----------------
__device__ float g_Dg[(long long)N_POSN * NJ];   // 64MB compact gathered columns, [n][j]
__device__ float g_rowmin[NB * N_POSN];          // min_g D[n,g] per batch, [b][n]
__device__ float g_S[NJ];                        // sum_n 1/(w+eps) per j
__device__ float g_t1[NB];                       // sum_n prob*minD per batch
__device__ float g_ne[NB];                       // sum_n prob per batch
__device__ int   g_maxbits;                      // max(dis_matrix) as int bits
__device__ int   g_pminbits;                     // min(prob_map)
__device__ int   g_pmaxbits;                     // max(prob_map)

// ---------------- kernel 0: init accumulators ----------------
__global__ void k_init() {
    int tid = blockIdx.x * blockDim.x + threadIdx.x;
    int nthreads = gridDim.x * blockDim.x;
    for (int j = tid; j < NJ; j += nthreads) g_S[j] = 0.0f;
    if (tid < NB) { g_t1[tid] = 0.0f; g_ne[tid] = 0.0f; }
    if (tid == 0) {
        g_maxbits  = 0;            // all dis values >= 0
        g_pminbits = 0x7F7FFFFF;   // FLT_MAX bits
        g_pmaxbits = 0;
    }
}

// ---------------- kernel 1: prob_map min/max ----------------
__global__ void k_probminmax(const float* __restrict__ pm, int n) {
    float lmin = __int_as_float(0x7F7FFFFF);
    float lmax = 0.0f;
    int stride = gridDim.x * blockDim.x;
    for (int i = blockIdx.x * blockDim.x + threadIdx.x; i < n; i += stride) {
        float v = pm[i];
        lmin = fminf(lmin, v);
        lmax = fmaxf(lmax, v);
    }
    #pragma unroll
    for (int o = 16; o; o >>= 1) {
        lmin = fminf(lmin, __shfl_xor_sync(0xFFFFFFFFu, lmin, o));
        lmax = fmaxf(lmax, __shfl_xor_sync(0xFFFFFFFFu, lmax, o));
    }
    if ((threadIdx.x & 31) == 0) {
        atomicMin(&g_pminbits, __float_as_int(lmin));
        atomicMax(&g_pmaxbits, __float_as_int(lmax));
    }
}

// ---------------- kernel 2: stream dis_matrix once ----------------
// Per row: load 32KB row -> smem (coalesced), accumulate global max,
// gather 2048 gt-columns from smem -> compact Dg (coalesced write),
// and per-batch min over the 512 gathered values (term1's min_g).
__global__ void __launch_bounds__(256) k_gather(const float* __restrict__ dis,
                                                const int* __restrict__ gt) {
    __shared__ float srow[N_POSN];
    __shared__ int   scols[NJ];
    __shared__ int   smin[NB];
    const int tid = threadIdx.x;

    for (int i = tid; i < NJ; i += 256) scols[i] = gt[i];

    float lmax = 0.0f;
    const int n0 = blockIdx.x * 8;  // 1024 CTAs x 8 rows = 8192

    for (int r = 0; r < 8; r++) {
        const int n = n0 + r;
        if (tid < NB) smin[tid] = 0x7F7FFFFF;

        const float4* src = reinterpret_cast<const float4*>(dis + (long long)n * N_POSN);
        float4* dst = reinterpret_cast<float4*>(srow);
        #pragma unroll
        for (int i = tid; i < N_POSN / 4; i += 256) {
            float4 v = src[i];
            dst[i] = v;
            lmax = fmaxf(lmax, fmaxf(fmaxf(v.x, v.y), fmaxf(v.z, v.w)));
        }
        __syncthreads();

        float lmin[4];
        #pragma unroll
        for (int b = 0; b < 4; b++) lmin[b] = __int_as_float(0x7F7FFFFF);

        float* out = g_Dg + (long long)n * NJ;
        #pragma unroll
        for (int it = 0; it < 8; it++) {      // j = it*256 + tid ; batch = it>>1
            int j = it * 256 + tid;
            float v = srow[scols[j]];
            out[j] = v;
            lmin[it >> 1] = fminf(lmin[it >> 1], v);
        }

        #pragma unroll
        for (int b = 0; b < 4; b++) {
            float m = lmin[b];
            #pragma unroll
            for (int o = 16; o; o >>= 1)
                m = fminf(m, __shfl_xor_sync(0xFFFFFFFFu, m, o));
            if ((tid & 31) == 0) atomicMin(&smin[b], __float_as_int(m));
        }
        __syncthreads();
        if (tid < NB) g_rowmin[tid * N_POSN + n] = __int_as_float(smin[tid]);
        __syncthreads();  // protect smin reset & srow overwrite next row
    }

    #pragma unroll
    for (int o = 16; o; o >>= 1)
        lmax = fmaxf(lmax, __shfl_xor_sync(0xFFFFFFFFu, lmax, o));
    if ((tid & 31) == 0) atomicMax(&g_maxbits, __float_as_int(lmax));
}

// ---------------- kernel 3: main reduction over compact Dg ----------------
// Thread tid owns j = tid + 512*k (k = batch index). Accumulates
// S[j] = sum_n 1/(w+eps), and (tid==0) term1 sums.
#define B_ROWS 64
__global__ void __launch_bounds__(512) k_main(const float* __restrict__ pm) {
    const float maxd = __int_as_float(g_maxbits);
    const float pmin = __int_as_float(g_pminbits);
    const float pmax = __int_as_float(g_pmaxbits);
    const float invr = 1.0f / (pmax - pmin);
    const float c0   = maxd + EPSF;

    const int tid = threadIdx.x;
    const int n0  = blockIdx.x * B_ROWS;   // 128 CTAs x 64 rows

    float acc[4] = {0.f, 0.f, 0.f, 0.f};
    float t1[4]  = {0.f, 0.f, 0.f, 0.f};
    float ne[4]  = {0.f, 0.f, 0.f, 0.f};

    #pragma unroll 2
    for (int r = 0; r < B_ROWS; r++) {
        const int n = n0 + r;
        const float* drow = g_Dg + (long long)n * NJ;
        #pragma unroll
        for (int k = 0; k < 4; k++) {
            float pmv = __ldg(pm + k * N_POSN + n);
            float p = fminf(fmaxf((pmv - pmin) * invr, 0.0f), 1.0f);
            float base = fmaf(-p, maxd, c0);         // (1-p)*maxd + eps
            float D = drow[tid + k * 512];
            float a = fmaf(p, D, base);              // w + eps
            acc[k] += __fdividef(1.0f, a);
            if (tid == 0) {
                t1[k] += p * g_rowmin[k * N_POSN + n];
                ne[k] += p;
            }
        }
    }

    #pragma unroll
    for (int k = 0; k < 4; k++)
        atomicAdd(&g_S[tid + k * 512], acc[k]);
    if (tid == 0) {
        #pragma unroll
        for (int b = 0; b < NB; b++) {
            atomicAdd(&g_t1[b], t1[b]);
            atomicAdd(&g_ne[b], ne[b]);
        }
    }
}

// ---------------- kernel 4: finalize scalar ----------------
// term2_mean = (1/(B*G)) * sum_j N/S[j] ; term1_mean = (1/B) sum_b t1[b]/(ne[b]+eps)
__global__ void __launch_bounds__(256) k_final(float* __restrict__ out) {
    __shared__ float ssum[256];
    const int tid = threadIdx.x;
    float s = 0.0f;
    for (int j = tid; j < NJ; j += 256)
        s += (float)N_POSN / g_S[j];
    ssum[tid] = s;
    __syncthreads();
    for (int o = 128; o; o >>= 1) {
        if (tid < o) ssum[tid] += ssum[tid + o];
        __syncthreads();
    }
    if (tid == 0) {
        float term2 = ssum[0] / (float)(NB * NG);
        float term1 = 0.0f;
        #pragma unroll
        for (int b = 0; b < NB; b++)
            term1 += g_t1[b] / (g_ne[b] + EPSF);
        term1 *= (1.0f / NB);
        out[0] = term1 + term2;
    }
}

// ---------------- launch ----------------
extern "C" void kernel_launch(void* const* d_in, const int* in_sizes, int n_in,
                              void* d_out, int out_size) {
    (void)in_sizes; (void)n_in; (void)out_size;
    const float* prob_map = (const float*)d_in[0];   // (4, 8192) f32
    const int*   gt       = (const int*)d_in[1];     // (4, 512)  i32
    const float* dis      = (const float*)d_in[2];   // (8192, 8192) f32
    float* out = (float*)d_out;

    k_init<<<8, 256>>>();
    k_probminmax<<<32, 256>>>(prob_map, NB * N_POSN);
    k_gather<<<1024, 256>>>(dis, gt);
    k_main<<<N_POSN / B_ROWS, 512>>>(prob_map);
    k_final<<<1, 256>>>(out);
}

// round 7
// speedup vs baseline: 1.4543x; 1.4543x over previous
#include <cuda_runtime.h>

#define N_POSN 8192
#define NB     4
#define NG     512
#define NJ     2048   /* NB*NG */
#define EPSF   1e-6f

// ---------------- device scratch (allocation-free) ----------------
__device__ float g_Dg[(long long)N_POSN * NJ];   // 64MB compact gathered columns, [n][j]
__device__ int   g_rowminbits[NB * N_POSN];      // min_g D[n,g] per batch (float bits), [b][n]
__device__ float g_S[NJ];                        // sum_n 1/(w+eps) per j
__device__ float g_t1[NB];                       // sum_n prob*minD per batch
__device__ float g_ne[NB];                       // sum_n prob per batch
__device__ int   g_maxbits;                      // max(dis_matrix) as int bits
__device__ int   g_pminbits;                     // min(prob_map)
__device__ int   g_pmaxbits;                     // max(prob_map)

// ---------------- kernel 0: init accumulators ----------------
__global__ void k_init() {
    int tid = blockIdx.x * blockDim.x + threadIdx.x;
    int nthreads = gridDim.x * blockDim.x;
    for (int j = tid; j < NJ; j += nthreads) g_S[j] = 0.0f;
    for (int i = tid; i < NB * N_POSN; i += nthreads) g_rowminbits[i] = 0x7F7FFFFF;
    if (tid < NB) { g_t1[tid] = 0.0f; g_ne[tid] = 0.0f; }
    if (tid == 0) {
        g_maxbits  = 0;            // all dis values >= 0
        g_pminbits = 0x7F7FFFFF;   // FLT_MAX bits
        g_pmaxbits = 0;
    }
}

// ---------------- kernel 1: prob_map min/max ----------------
__global__ void k_probminmax(const float* __restrict__ pm, int n) {
    float lmin = __int_as_float(0x7F7FFFFF);
    float lmax = 0.0f;
    int stride = gridDim.x * blockDim.x;
    for (int i = blockIdx.x * blockDim.x + threadIdx.x; i < n; i += stride) {
        float v = pm[i];
        lmin = fminf(lmin, v);
        lmax = fmaxf(lmax, v);
    }
    #pragma unroll
    for (int o = 16; o; o >>= 1) {
        lmin = fminf(lmin, __shfl_xor_sync(0xFFFFFFFFu, lmin, o));
        lmax = fmaxf(lmax, __shfl_xor_sync(0xFFFFFFFFu, lmax, o));
    }
    if ((threadIdx.x & 31) == 0) {
        atomicMin(&g_pminbits, __float_as_int(lmin));
        atomicMax(&g_pmaxbits, __float_as_int(lmax));
    }
}

// ---------------- kernel 2: stream dis_matrix once (register prefetch) ----------------
// Per row: issue next row's LDG.128s into registers FIRST (DRAM latency hides
// behind the gather of the current row), gather row r from smem -> compact Dg,
// then barrier, store prefetched regs -> smem, barrier.
// Static smem: 32KB row + 8KB cols = 40KB (fits the 48KB static limit).
__global__ void __launch_bounds__(256) k_gather(const float* __restrict__ dis,
                                                const int* __restrict__ gt) {
    __shared__ float srow[N_POSN];     // 32KB
    __shared__ int   scols[NJ];        // 8KB
    const int tid = threadIdx.x;

    for (int i = tid; i < NJ; i += 256) scols[i] = gt[i];

    const int n0 = blockIdx.x * 8;     // 1024 CTAs x 8 rows
    float lmax = 0.0f;

    // prologue: row n0 -> srow
    {
        const float4* src = reinterpret_cast<const float4*>(dis + (long long)n0 * N_POSN);
        float4* dst = reinterpret_cast<float4*>(srow);
        #pragma unroll
        for (int i = 0; i < 8; i++) {
            float4 v = src[i * 256 + tid];
            lmax = fmaxf(lmax, fmaxf(fmaxf(v.x, v.y), fmaxf(v.z, v.w)));
            dst[i * 256 + tid] = v;
        }
    }
    __syncthreads();

    #pragma unroll
    for (int r = 0; r < 8; r++) {
        const int n = n0 + r;

        // 1) issue next row's loads NOW — they land while we gather below
        float4 v[8];
        if (r < 7) {
            const float4* src = reinterpret_cast<const float4*>(dis + (long long)(n + 1) * N_POSN);
            #pragma unroll
            for (int i = 0; i < 8; i++) v[i] = src[i * 256 + tid];
        }

        // 2) gather row n from srow -> compact Dg (coalesced), track per-batch min
        float* out = g_Dg + (long long)n * NJ;
        float lmin[4];
        #pragma unroll
        for (int b = 0; b < 4; b++) lmin[b] = __int_as_float(0x7F7FFFFF);
        #pragma unroll
        for (int it = 0; it < 8; it++) {      // j = it*256 + tid ; batch = it>>1
            int j = it * 256 + tid;
            float val = srow[scols[j]];
            out[j] = val;
            lmin[it >> 1] = fminf(lmin[it >> 1], val);
        }

        #pragma unroll
        for (int b = 0; b < 4; b++) {
            float m = lmin[b];
            #pragma unroll
            for (int o = 16; o; o >>= 1)
                m = fminf(m, __shfl_xor_sync(0xFFFFFFFFu, m, o));
            if ((tid & 31) == 0)
                atomicMin(&g_rowminbits[b * N_POSN + n], __float_as_int(m));
        }
        __syncthreads();   // everyone done reading srow

        // 3) store prefetched row into srow + fold into max
        if (r < 7) {
            float4* dst = reinterpret_cast<float4*>(srow);
            #pragma unroll
            for (int i = 0; i < 8; i++) {
                float4 w = v[i];
                lmax = fmaxf(lmax, fmaxf(fmaxf(w.x, w.y), fmaxf(w.z, w.w)));
                dst[i * 256 + tid] = w;
            }
            __syncthreads();   // srow visible for next gather
        }
    }

    #pragma unroll
    for (int o = 16; o; o >>= 1)
        lmax = fmaxf(lmax, __shfl_xor_sync(0xFFFFFFFFu, lmax, o));
    if ((tid & 31) == 0) atomicMax(&g_maxbits, __float_as_int(lmax));
}

// ---------------- kernel 3: main reduction over compact Dg ----------------
// Thread tid owns 4 consecutive j = [4*tid, 4*tid+4), all in batch k = tid>>7.
// One LDG.128 per row per thread; 512 CTAs x 16 rows.
#define B_ROWS 16
__global__ void __launch_bounds__(512) k_main(const float* __restrict__ pm) {
    const float maxd = __int_as_float(g_maxbits);
    const float pmin = __int_as_float(g_pminbits);
    const float pmax = __int_as_float(g_pmaxbits);
    const float invr = 1.0f / (pmax - pmin);
    const float c0   = maxd + EPSF;

    const int tid = threadIdx.x;
    const int k   = tid >> 7;                 // batch (warp-uniform)
    const int n0  = blockIdx.x * B_ROWS;      // 512 CTAs

    float4 acc = make_float4(0.f, 0.f, 0.f, 0.f);
    const float4* Dg4 = reinterpret_cast<const float4*>(g_Dg);

    #pragma unroll 4
    for (int r = 0; r < B_ROWS; r++) {
        const int n = n0 + r;
        float pmv  = __ldg(pm + k * N_POSN + n);          // warp-uniform load
        float p    = fminf(fmaxf((pmv - pmin) * invr, 0.0f), 1.0f);
        float base = fmaf(-p, maxd, c0);                  // (1-p)*maxd + eps
        float4 d   = Dg4[(long long)n * 512 + tid];
        acc.x += __fdividef(1.0f, fmaf(p, d.x, base));
        acc.y += __fdividef(1.0f, fmaf(p, d.y, base));
        acc.z += __fdividef(1.0f, fmaf(p, d.z, base));
        acc.w += __fdividef(1.0f, fmaf(p, d.w, base));
    }

    atomicAdd(&g_S[4 * tid + 0], acc.x);
    atomicAdd(&g_S[4 * tid + 1], acc.y);
    atomicAdd(&g_S[4 * tid + 2], acc.z);
    atomicAdd(&g_S[4 * tid + 3], acc.w);

    // term1: threads 0..63 (warps 0,1 fully) each handle one (b, row) pair,
    // segment-reduce the 16-lane groups, 4 leader atomics per CTA.
    if (tid < 64) {
        const int b  = tid >> 4;
        const int n  = n0 + (tid & 15);
        float pmv = __ldg(pm + b * N_POSN + n);
        float p   = fminf(fmaxf((pmv - pmin) * invr, 0.0f), 1.0f);
        float rm  = __int_as_float(g_rowminbits[b * N_POSN + n]);
        float t1  = p * rm;
        float ne  = p;
        #pragma unroll
        for (int o = 8; o; o >>= 1) {
            t1 += __shfl_xor_sync(0xFFFFFFFFu, t1, o);
            ne += __shfl_xor_sync(0xFFFFFFFFu, ne, o);
        }
        if ((tid & 15) == 0) {
            atomicAdd(&g_t1[b], t1);
            atomicAdd(&g_ne[b], ne);
        }
    }
}

// ---------------- kernel 4: finalize scalar ----------------
// term2 = (1/(B*G)) * sum_j N/S[j] ; term1 = (1/B) sum_b t1[b]/(ne[b]+eps)
__global__ void __launch_bounds__(256) k_final(float* __restrict__ out) {
    __shared__ float ssum[256];
    const int tid = threadIdx.x;
    float s = 0.0f;
    for (int j = tid; j < NJ; j += 256)
        s += (float)N_POSN / g_S[j];
    ssum[tid] = s;
    __syncthreads();
    for (int o = 128; o; o >>= 1) {
        if (tid < o) ssum[tid] += ssum[tid + o];
        __syncthreads();
    }
    if (tid == 0) {
        float term2 = ssum[0] / (float)(NB * NG);
        float term1 = 0.0f;
        #pragma unroll
        for (int b = 0; b < NB; b++)
            term1 += g_t1[b] / (g_ne[b] + EPSF);
        term1 *= (1.0f / NB);
        out[0] = term1 + term2;
    }
}

// ---------------- launch ----------------
extern "C" void kernel_launch(void* const* d_in, const int* in_sizes, int n_in,
                              void* d_out, int out_size) {
    (void)in_sizes; (void)n_in; (void)out_size;
    const float* prob_map = (const float*)d_in[0];   // (4, 8192) f32
    const int*   gt       = (const int*)d_in[1];     // (4, 512)  i32
    const float* dis      = (const float*)d_in[2];   // (8192, 8192) f32
    float* out = (float*)d_out;

    k_init<<<128, 256>>>();
    k_probminmax<<<32, 256>>>(prob_map, NB * N_POSN);
    k_gather<<<1024, 256>>>(dis, gt);
    k_main<<<N_POSN / B_ROWS, 512>>>(prob_map);
    k_final<<<1, 256>>>(out);
}

// round 8
// speedup vs baseline: 2.0661x; 1.4206x over previous
#include <cuda_runtime.h>

#define N_POSN 8192
#define NB     4
#define NG     512
#define NJ     2048   /* NB*NG */
#define NREP   8
#define EPSF   1e-6f

// ---------------- device scratch (allocation-free) ----------------
__device__ float g_Dg[(long long)N_POSN * NJ];   // 64MB compact gathered columns, [n][j]
__device__ float g_rowmin[NB * N_POSN];          // min_g D[n,g] per batch, [b][n] (plain stores)
__device__ float g_S8[NREP][NJ];                 // replicated sum_n 1/(w+eps)
__device__ float g_t1[NB];                       // sum_n prob*minD per batch
__device__ float g_ne[NB];                       // sum_n prob per batch
__device__ int   g_maxbits;                      // max(dis_matrix) bits; atomicMax, idempotent (dis>=0)
__device__ float g_pmin;                         // min(prob_map)  (plain store from k_gather CTA0)
__device__ float g_pmax;                         // max(prob_map)

// ---------------- kernel 1: stream dis_matrix once (register prefetch) ----------------
// Per row: issue next row's LDG.128s into registers FIRST (DRAM latency hides
// behind the gather of the current row), gather row r from smem -> compact Dg,
// smem-reduce per-batch rowmin (plain store, no atomics), barrier, store
// prefetched regs -> smem, barrier. CTA 0 additionally zeroes the replicated
// accumulators + t1/ne and computes prob_map min/max (hidden in the wave).
__global__ void __launch_bounds__(256) k_gather(const float* __restrict__ dis,
                                                const int* __restrict__ gt,
                                                const float* __restrict__ pm) {
    __shared__ float srow[N_POSN];     // 32KB
    __shared__ int   scols[NJ];        // 8KB
    __shared__ int   sminw[NB][8];     // per-warp per-batch min bits
    __shared__ int   spmin[8], spmax[8];
    const int tid = threadIdx.x;
    const int wid = tid >> 5;

    for (int i = tid; i < NJ; i += 256) scols[i] = gt[i];

    const int n0 = blockIdx.x * 8;     // 1024 CTAs x 8 rows
    float lmax = 0.0f;

    // prologue: row n0 -> srow (streaming loads: don't thrash Dg out of L2)
    {
        const float4* src = reinterpret_cast<const float4*>(dis + (long long)n0 * N_POSN);
        float4* dst = reinterpret_cast<float4*>(srow);
        #pragma unroll
        for (int i = 0; i < 8; i++) {
            float4 v = __ldcs(src + i * 256 + tid);
            lmax = fmaxf(lmax, fmaxf(fmaxf(v.x, v.y), fmaxf(v.z, v.w)));
            dst[i * 256 + tid] = v;
        }
    }
    __syncthreads();

    #pragma unroll
    for (int r = 0; r < 8; r++) {
        const int n = n0 + r;

        // 1) issue next row's loads NOW — they land while we gather below
        float4 v[8];
        if (r < 7) {
            const float4* src = reinterpret_cast<const float4*>(dis + (long long)(n + 1) * N_POSN);
            #pragma unroll
            for (int i = 0; i < 8; i++) v[i] = __ldcs(src + i * 256 + tid);
        }

        // 2) gather row n from srow -> compact Dg (coalesced), track per-batch min
        float* out = g_Dg + (long long)n * NJ;
        float lmin[4];
        #pragma unroll
        for (int b = 0; b < 4; b++) lmin[b] = __int_as_float(0x7F7FFFFF);
        #pragma unroll
        for (int it = 0; it < 8; it++) {      // j = it*256 + tid ; batch = it>>1
            int j = it * 256 + tid;
            float val = srow[scols[j]];
            out[j] = val;
            lmin[it >> 1] = fminf(lmin[it >> 1], val);
        }

        #pragma unroll
        for (int b = 0; b < 4; b++) {
            float m = lmin[b];
            #pragma unroll
            for (int o = 16; o; o >>= 1)
                m = fminf(m, __shfl_xor_sync(0xFFFFFFFFu, m, o));
            if ((tid & 31) == 0) sminw[b][wid] = __float_as_int(m);
        }
        __syncthreads();   // srow reads + sminw writes done

        // 3a) threads 0-3: finish rowmin reduce, plain store
        if (tid < NB) {
            int mb = sminw[tid][0];
            #pragma unroll
            for (int w = 1; w < 8; w++) mb = min(mb, sminw[tid][w]);
            g_rowmin[tid * N_POSN + n] = __int_as_float(mb);
        }
        // 3b) store prefetched row into srow + fold into max
        if (r < 7) {
            float4* dst = reinterpret_cast<float4*>(srow);
            #pragma unroll
            for (int i = 0; i < 8; i++) {
                float4 w = v[i];
                lmax = fmaxf(lmax, fmaxf(fmaxf(w.x, w.y), fmaxf(w.z, w.w)));
                dst[i * 256 + tid] = w;
            }
            __syncthreads();   // srow visible for next gather; sminw safe to rewrite
        }
    }

    #pragma unroll
    for (int o = 16; o; o >>= 1)
        lmax = fmaxf(lmax, __shfl_xor_sync(0xFFFFFFFFu, lmax, o));
    if ((tid & 31) == 0) atomicMax(&g_maxbits, __float_as_int(lmax));

    // ---- CTA 0 extra duties (ordered before k_main by the kernel boundary) ----
    if (blockIdx.x == 0) {
        float* s8 = &g_S8[0][0];
        for (int i = tid; i < NREP * NJ; i += 256) s8[i] = 0.0f;
        if (tid < NB) { g_t1[tid] = 0.0f; g_ne[tid] = 0.0f; }

        // prob_map min/max (32KB)
        float mn = __int_as_float(0x7F7FFFFF);
        float mx = -__int_as_float(0x7F7FFFFF);
        const float4* pm4 = reinterpret_cast<const float4*>(pm);
        for (int i = tid; i < (NB * N_POSN) / 4; i += 256) {
            float4 v = pm4[i];
            mn = fminf(mn, fminf(fminf(v.x, v.y), fminf(v.z, v.w)));
            mx = fmaxf(mx, fmaxf(fmaxf(v.x, v.y), fmaxf(v.z, v.w)));
        }
        #pragma unroll
        for (int o = 16; o; o >>= 1) {
            mn = fminf(mn, __shfl_xor_sync(0xFFFFFFFFu, mn, o));
            mx = fmaxf(mx, __shfl_xor_sync(0xFFFFFFFFu, mx, o));
        }
        if ((tid & 31) == 0) { spmin[wid] = __float_as_int(mn); spmax[wid] = __float_as_int(mx); }
        __syncthreads();
        if (tid == 0) {
            int a = spmin[0], b = spmax[0];
            #pragma unroll
            for (int w = 1; w < 8; w++) { a = min(a, spmin[w]); b = max(b, spmax[w]); }
            g_pmin = __int_as_float(a);
            g_pmax = __int_as_float(b);
        }
    }
}

// ---------------- kernel 2: main reduction over compact Dg ----------------
// Thread tid owns 4 consecutive j = [4*tid, 4*tid+4), batch k = tid>>7.
// Explicit 8-deep register load batching for MLP; 8-way replicated S accumulator.
#define B_ROWS 16
__global__ void __launch_bounds__(512) k_main(const float* __restrict__ pm) {
    const float maxd = __int_as_float(g_maxbits);
    const float pmin = g_pmin;
    const float invr = 1.0f / (g_pmax - pmin);
    const float c0   = maxd + EPSF;

    const int tid = threadIdx.x;
    const int k   = tid >> 7;                 // batch (warp-uniform)
    const int n0  = blockIdx.x * B_ROWS;      // 512 CTAs

    float4 acc = make_float4(0.f, 0.f, 0.f, 0.f);
    const float4* Dg4 = reinterpret_cast<const float4*>(g_Dg);

    #pragma unroll
    for (int c = 0; c < B_ROWS / 8; c++) {
        float4 d[8];
        float  pv[8];
        #pragma unroll
        for (int i = 0; i < 8; i++)
            d[i] = Dg4[(long long)(n0 + c * 8 + i) * 512 + tid];
        #pragma unroll
        for (int i = 0; i < 8; i++)
            pv[i] = __ldg(pm + k * N_POSN + n0 + c * 8 + i);   // warp-uniform, cached
        #pragma unroll
        for (int i = 0; i < 8; i++) {
            float p    = fminf(fmaxf((pv[i] - pmin) * invr, 0.0f), 1.0f);
            float base = fmaf(-p, maxd, c0);                   // (1-p)*maxd + eps
            acc.x += __fdividef(1.0f, fmaf(p, d[i].x, base));
            acc.y += __fdividef(1.0f, fmaf(p, d[i].y, base));
            acc.z += __fdividef(1.0f, fmaf(p, d[i].z, base));
            acc.w += __fdividef(1.0f, fmaf(p, d[i].w, base));
        }
    }

    float* Srep = g_S8[blockIdx.x & (NREP - 1)];
    atomicAdd(&Srep[4 * tid + 0], acc.x);
    atomicAdd(&Srep[4 * tid + 1], acc.y);
    atomicAdd(&Srep[4 * tid + 2], acc.z);
    atomicAdd(&Srep[4 * tid + 3], acc.w);

    // term1: threads 0..63 each handle one (b, row) pair; 16-lane segment reduce.
    if (tid < 64) {
        const int b  = tid >> 4;
        const int n  = n0 + (tid & 15);
        float pmv = __ldg(pm + b * N_POSN + n);
        float p   = fminf(fmaxf((pmv - pmin) * invr, 0.0f), 1.0f);
        float rm  = g_rowmin[b * N_POSN + n];
        float t1  = p * rm;
        float ne  = p;
        #pragma unroll
        for (int o = 8; o; o >>= 1) {
            t1 += __shfl_xor_sync(0xFFFFFFFFu, t1, o);
            ne += __shfl_xor_sync(0xFFFFFFFFu, ne, o);
        }
        if ((tid & 15) == 0) {
            atomicAdd(&g_t1[b], t1);
            atomicAdd(&g_ne[b], ne);
        }
    }
}

// ---------------- kernel 3: finalize scalar ----------------
// Reduce 8 replicas (64KB, L2-hot), then term2 = (1/(B*G)) sum_j N/S[j];
// term1 = (1/B) sum_b t1[b]/(ne[b]+eps).
__global__ void __launch_bounds__(512) k_final(float* __restrict__ out) {
    __shared__ float ssum[512];
    const int tid = threadIdx.x;
    float s = 0.0f;
    #pragma unroll
    for (int m = 0; m < NJ / 512; m++) {
        int j = tid + m * 512;
        float S = 0.0f;
        #pragma unroll
        for (int rp = 0; rp < NREP; rp++) S += g_S8[rp][j];
        s += (float)N_POSN / S;
    }
    ssum[tid] = s;
    __syncthreads();
    for (int o = 256; o; o >>= 1) {
        if (tid < o) ssum[tid] += ssum[tid + o];
        __syncthreads();
    }
    if (tid == 0) {
        float term2 = ssum[0] / (float)(NB * NG);
        float term1 = 0.0f;
        #pragma unroll
        for (int b = 0; b < NB; b++)
            term1 += g_t1[b] / (g_ne[b] + EPSF);
        term1 *= (1.0f / NB);
        out[0] = term1 + term2;
    }
}

// ---------------- launch ----------------
extern "C" void kernel_launch(void* const* d_in, const int* in_sizes, int n_in,
                              void* d_out, int out_size) {
    (void)in_sizes; (void)n_in; (void)out_size;
    const float* prob_map = (const float*)d_in[0];   // (4, 8192) f32
    const int*   gt       = (const int*)d_in[1];     // (4, 512)  i32
    const float* dis      = (const float*)d_in[2];   // (8192, 8192) f32
    float* out = (float*)d_out;

    k_gather<<<1024, 256>>>(dis, gt, prob_map);
    k_main<<<N_POSN / B_ROWS, 512>>>(prob_map);
    k_final<<<1, 512>>>(out);
}